// round 16
// baseline (speedup 1.0000x reference)
#include <cuda_runtime.h>
#include <cuda_fp16.h>
#include <cstdint>
#include <cstddef>

// Problem constants
#define B_    4
#define CI_   256
#define CO_   256
#define H_    64
#define W_    64
#define HW_   4096
#define KK_   9
#define KDIM  2304          // CI_*KK_

// channel-last fp16 input, stored as u32 (half2 pairs): xT[(b*4096+hw)*256 + ci]
__device__ uint32_t g_xT[(size_t)B_ * HW_ * CI_ / 2];   // 8.4 MB
// fp16 repacked weight: w[co][k'] with k' = kk*256 + ci
__device__ __half g_w[(size_t)CO_ * KDIM];              // 1.2 MB

// ---------------------------------------------------------------------------
// Helpers
// ---------------------------------------------------------------------------
__device__ __forceinline__ uint32_t smem_u32(const void* p) {
    uint32_t a;
    asm("{ .reg .u64 t; cvta.to.shared.u64 t, %1; cvt.u32.u64 %0, t; }" : "=r"(a) : "l"(p));
    return a;
}
__device__ __forceinline__ void cp_async16(uint32_t dst, const void* src) {
    asm volatile("cp.async.cg.shared.global [%0], [%1], 16;" :: "r"(dst), "l"(src));
}
#define CP_COMMIT() asm volatile("cp.async.commit_group;" ::: "memory")
#define CP_WAIT1()  asm volatile("cp.async.wait_group 1;" ::: "memory")

__device__ __forceinline__ void ldsm4(uint32_t& r0, uint32_t& r1, uint32_t& r2,
                                      uint32_t& r3, uint32_t addr) {
    asm volatile("ldmatrix.sync.aligned.m8n8.x4.shared.b16 {%0,%1,%2,%3}, [%4];"
                 : "=r"(r0), "=r"(r1), "=r"(r2), "=r"(r3) : "r"(addr));
}
__device__ __forceinline__ void mma16816(float* c, const uint32_t* a, const uint32_t* b) {
    asm volatile(
        "mma.sync.aligned.m16n8k16.row.col.f32.f16.f16.f32 "
        "{%0,%1,%2,%3}, {%4,%5,%6,%7}, {%8,%9}, {%0,%1,%2,%3};"
        : "+f"(c[0]), "+f"(c[1]), "+f"(c[2]), "+f"(c[3])
        : "r"(a[0]), "r"(a[1]), "r"(a[2]), "r"(a[3]), "r"(b[0]), "r"(b[1]));
}
__device__ __forceinline__ void sts64(uint32_t addr, uint32_t v0, uint32_t v1) {
    asm volatile("st.shared.v2.b32 [%0], {%1, %2};" :: "r"(addr), "r"(v0), "r"(v1) : "memory");
}

// ---------------------------------------------------------------------------
// Kernel 1: merged prep.
//   z < 4 : tiled transpose+convert  x[b][ci][hw] (f32) -> xT[b][hw][ci] (f16)
//   z == 4: grid-stride weight repack g_w[co][kk*256+ci] = (half) W[co][ci][kk]
// ---------------------------------------------------------------------------
__global__ __launch_bounds__(256) void prep_kernel(
    const float* __restrict__ x, const float* __restrict__ w)
{
    int z = blockIdx.z;
    int tid = threadIdx.x;

    if (z < B_) {
        __shared__ float sm[32][33];
        int hw0 = blockIdx.x * 32;
        int ci0 = blockIdx.y * 32;
        int b   = z;
        int tx = tid & 31, ty = tid >> 5;      // (32, 8)

        const float* xb = x + (size_t)b * CI_ * HW_;
        #pragma unroll
        for (int i = 0; i < 4; i++)
            sm[ty + i * 8][tx] = xb[(size_t)(ci0 + ty + i * 8) * HW_ + hw0 + tx];
        __syncthreads();

        uint32_t* xtb = g_xT + (size_t)b * HW_ * CI_ / 2;
        #pragma unroll
        for (int rep = 0; rep < 2; rep++) {
            int t = tid + rep * 256;
            int hwl = t >> 4;                  // 0..31
            int cip = t & 15;                  // ci pair index
            __half2 h2 = __floats2half2_rn(sm[2 * cip][hwl], sm[2 * cip + 1][hwl]);
            xtb[(size_t)(hw0 + hwl) * (CI_ / 2) + ci0 / 2 + cip] = *(uint32_t*)&h2;
        }
    } else {
        int rb = blockIdx.x * gridDim.y + blockIdx.y;     // 0..1023
        for (int ck = rb; ck < CO_ * KK_; ck += 1024) {   // co*9 + kk
            int co = ck / KK_, kk = ck % KK_;
            g_w[(size_t)ck * CI_ + tid] =
                __float2half(w[((size_t)co * CI_ + tid) * KK_ + kk]);
        }
    }
}

// ---------------------------------------------------------------------------
// Kernel 2: warp-specialized fused deformable im2col + HMMA GEMM
// CTA: 128 px x 256 co, 640 threads = 16 consumer warps (2x8 grid, warp
// tile 64x32, acc 64 regs) + 4 producer warps (one per SMSP).
// Consumers: pure ldsm+mma stream. Producers: A gather (pairwise LDG.64 +
// HFMA2 + STS.64, 32 px/warp/chunk) + B cp.async staging.
// Double-buffered A and B; B(c+2) staged with a full chunk of slack
// (wait_group 1). SW128 swizzle: ch ^= (row&7). x2 unrolled stages.
// 1 CTA/SM, grid 128.
// ---------------------------------------------------------------------------
#define BM 128
#define BK 64
#define NCH (KDIM / BK)       // 36
#define NTHR 640
#define SM_A0   0             // 2 x 16384 (A: 128 x 64 half)
#define SM_B0   32768         // 2 x 32768 (B: 256 x 64 half)
#define SM_IDX  98304         // int4  [128]  (2 KB)  per-pixel corner offsets
#define SM_WTS  100352        // uint4 [128]  (2 KB)  per-pixel half2 weights
#define SM_TOTAL 102400
#define EPI_STRIDE 130        // floats per epilogue row (even -> aligned float2)

__global__ __launch_bounds__(NTHR, 1) void fused_kernel(
    const float* __restrict__ offset, float* __restrict__ out)
{
    extern __shared__ char smem[];
    uint32_t sb = smem_u32(smem);
    int tid = threadIdx.x, wid = tid >> 5, l = tid & 31;
    int pt = blockIdx.x;      // pixel tile 0..31
    int b  = blockIdx.y;

    int4*  idx_sm = (int4*)(smem + SM_IDX);    // [128] per-pixel
    uint4* wts_sm = (uint4*)(smem + SM_WTS);   // [128]

    const float*  offb = offset + (size_t)b * 18 * HW_;
    const __half* xTb  = (const __half*)g_xT + (size_t)b * HW_ * CI_;

    bool is_prod = (wid >= 16);
    int  pw = wid - 16;       // producer warp 0..3 (owns px [pw*32, pw*32+32))

    // ---- producer: bilinear corner offsets/weights for 32 pixels at tap kk
    auto calc_off = [&](int kk) {
        int pg = pt * BM + pw * 32 + l;
        int h = pg >> 6, w = pg & 63;
        float offy = offb[(size_t)(2 * kk)     * HW_ + pg];
        float offx = offb[(size_t)(2 * kk + 1) * HW_ + pg];
        int i = kk / 3, j = kk % 3;
        float py = (float)(h + i) + offy;   // padded coords
        float px = (float)(w + j) + offx;
        float y0f = floorf(py), x0f = floorf(px);
        float ly = py - y0f, lx = px - x0f;
        int y0 = (int)y0f - 1, x0 = (int)x0f - 1;   // unpadded
        float wt[4] = { (1.f - ly) * (1.f - lx), (1.f - ly) * lx,
                        ly * (1.f - lx),          ly * lx };
        int fl[4];
        uint32_t wh[4];
        #pragma unroll
        for (int c = 0; c < 4; c++) {
            int yi = y0 + (c >> 1), xi = x0 + (c & 1);
            bool v = (yi >= 0) & (yi < H_) & (xi >= 0) & (xi < W_);
            fl[c] = v ? (yi * W_ + xi) * CI_ : 0;   // half-element offset
            if (!v) wt[c] = 0.f;
            __half2 h2 = __half2half2(__float2half(wt[c]));
            wh[c] = *(uint32_t*)&h2;
        }
        idx_sm[pw * 32 + l] = make_int4(fl[0], fl[1], fl[2], fl[3]);
        wts_sm[pw * 32 + l] = make_uint4(wh[0], wh[1], wh[2], wh[3]);
        __syncwarp();
    };

    // producer gather lane mapping: lane&15 -> ci quad, lane>>4 -> px of pair
    int lh = l >> 4;
    int lq = l & 15;
    uint2 cv[2][2][4];        // double-buffered: [buf][pair][corner]

    auto gatherG = [&](int c, int g, int buf) {      // group g = 4 pixels
        int cin = (c & 3) * 64;
        const __half* xp = xTb + cin + 4 * lq;
        #pragma unroll
        for (int q2 = 0; q2 < 2; q2++) {
            int4 f = idx_sm[pw * 32 + g * 4 + q2 * 2 + lh];
            cv[buf][q2][0] = *(const uint2*)(xp + f.x);
            cv[buf][q2][1] = *(const uint2*)(xp + f.y);
            cv[buf][q2][2] = *(const uint2*)(xp + f.z);
            cv[buf][q2][3] = *(const uint2*)(xp + f.w);
        }
    };
    auto convertG = [&](int sn, int g, int buf) {
        uint32_t sa = sb + SM_A0 + sn * 16384;
        #pragma unroll
        for (int q2 = 0; q2 < 2; q2++) {
            uint4 w4 = wts_sm[pw * 32 + g * 4 + q2 * 2 + lh];
            __half2 va = __hmul2(*(__half2*)&cv[buf][q2][0].x, *(__half2*)&w4.x);
            __half2 vb = __hmul2(*(__half2*)&cv[buf][q2][0].y, *(__half2*)&w4.x);
            va = __hfma2(*(__half2*)&cv[buf][q2][1].x, *(__half2*)&w4.y, va);
            vb = __hfma2(*(__half2*)&cv[buf][q2][1].y, *(__half2*)&w4.y, vb);
            va = __hfma2(*(__half2*)&cv[buf][q2][2].x, *(__half2*)&w4.z, va);
            vb = __hfma2(*(__half2*)&cv[buf][q2][2].y, *(__half2*)&w4.z, vb);
            va = __hfma2(*(__half2*)&cv[buf][q2][3].x, *(__half2*)&w4.w, va);
            vb = __hfma2(*(__half2*)&cv[buf][q2][3].y, *(__half2*)&w4.w, vb);
            int p = pw * 32 + g * 4 + q2 * 2 + lh;   // A row 0..127
            int ch = lq >> 1;
            sts64(sa + p * 128 + ((ch ^ (p & 7)) << 4) + ((lq & 1) << 3),
                  *(uint32_t*)&va, *(uint32_t*)&vb);
        }
    };
    auto gatherconvert_chunk = [&](int c, int sn) {  // 32 px = 8 groups
        gatherG(c, 0, 0);
        #pragma unroll
        for (int g = 1; g < 8; g++) {
            gatherG(c, g, g & 1);
            convertG(sn, g - 1, (g - 1) & 1);
        }
        convertG(sn, 7, 1);
    };
    auto stage_B = [&](int c, int sn) {
        int k0 = c * BK;
        uint32_t sw = sb + SM_B0 + sn * 32768;
        int ptid = tid - 512;                 // 0..127
        #pragma unroll
        for (int i = 0; i < 16; i++) {        // 2048 16B chunks / 128 thr
            int id = ptid + i * 128;
            int r = id >> 3, ch = id & 7;
            cp_async16(sw + r * 128 + ((ch ^ (r & 7)) << 4),
                       g_w + (size_t)r * KDIM + k0 + ch * 8);
        }
    };

    // ---- consumer state
    float acc[4][4][4];
    #pragma unroll
    for (int a = 0; a < 4; a++)
        #pragma unroll
        for (int bb = 0; bb < 4; bb++)
            #pragma unroll
            for (int cc = 0; cc < 4; cc++) acc[a][bb][cc] = 0.f;

    int wm = wid >> 3;        // 0..1: px half (consumers)
    int wn = wid & 7;         // 0..7: co slab
    int laneA_r = l & 15;
    int laneA_c = l >> 4;
    int laneB_r = (l & 7) + ((l >> 4) << 3);
    int laneB_c = (l >> 3) & 1;

    auto mma_steps = [&](int s, int st0) {
        uint32_t sa = sb + SM_A0 + s * 16384;
        uint32_t sw = sb + SM_B0 + s * 32768;
        #pragma unroll
        for (int st = st0; st < st0 + 2; st++) {     // k16 steps
            uint32_t af[4][4];
            #pragma unroll
            for (int mi = 0; mi < 4; mi++) {
                int r = wm * 64 + mi * 16 + laneA_r;
                int ch = 2 * st + laneA_c;
                ldsm4(af[mi][0], af[mi][1], af[mi][2], af[mi][3],
                      sa + r * 128 + ((ch ^ (r & 7)) << 4));
            }
            uint32_t bf[4][2];
            #pragma unroll
            for (int nj = 0; nj < 2; nj++) {
                int r = wn * 32 + nj * 16 + laneB_r;
                int ch = 2 * st + laneB_c;
                uint32_t r0, r1, r2, r3;
                ldsm4(r0, r1, r2, r3,
                      sw + r * 128 + ((ch ^ (r & 7)) << 4));
                bf[nj * 2][0] = r0;      bf[nj * 2][1] = r1;
                bf[nj * 2 + 1][0] = r2;  bf[nj * 2 + 1][1] = r3;
            }
            #pragma unroll
            for (int mi = 0; mi < 4; mi++)
                #pragma unroll
                for (int ni = 0; ni < 4; ni++)
                    mma16816(acc[mi][ni], af[mi], bf[ni]);
        }
    };

    // one chunk; s is a literal (x2 unroll) so stage bases const-fold
    auto chunk_body = [&](int c, int s) {
        int sn = s ^ 1;
        int cn = c + 1;
        if (!is_prod) {
            mma_steps(s, 0);
            mma_steps(s, 2);
        } else if (cn < NCH) {
            if ((cn & 3) == 0) calc_off(cn >> 2);
            gatherconvert_chunk(cn, sn);
        }
        __syncthreads();                 // stage s consumed / A(sn) written
        if (is_prod) {
            if (c + 2 < NCH) stage_B(c + 2, s);
            CP_COMMIT();
            CP_WAIT1();                  // B(c+1) resident
        }
        __syncthreads();                 // visibility of B(c+1) + A(c+1)
    };

    // ---- prologue ----
    if (is_prod) {
        calc_off(0);
        stage_B(0, 0); CP_COMMIT();
        stage_B(1, 1); CP_COMMIT();
        gatherconvert_chunk(0, 0);
        CP_WAIT1();                      // B(0) resident
    }
    __syncthreads();

    // ---- mainloop (unrolled x2: stage index is a literal) ----
    for (int c0 = 0; c0 < NCH; c0 += 2) {
        chunk_body(c0, 0);
        chunk_body(c0 + 1, 1);
    }

    // ---- epilogue: two co-halves staged through smem, coalesced drain ----
    {
        float* eb = (float*)smem;        // [128 co][EPI_STRIDE]
        #pragma unroll
        for (int half = 0; half < 2; half++) {
            if (!is_prod && ((wn >> 2) == half)) {
                int mrow = l >> 2;
                int ncol = (wn & 3) * 32 + ((l & 3) << 1);
                #pragma unroll
                for (int mi = 0; mi < 4; mi++) {
                    #pragma unroll
                    for (int ni = 0; ni < 4; ni++) {
                        int m = wm * 64 + mrow + mi * 16;
                        int n = ncol + ni * 8;
                        eb[(size_t)n * EPI_STRIDE + m]           = acc[mi][ni][0];
                        eb[(size_t)(n + 1) * EPI_STRIDE + m]     = acc[mi][ni][1];
                        eb[(size_t)n * EPI_STRIDE + m + 8]       = acc[mi][ni][2];
                        eb[(size_t)(n + 1) * EPI_STRIDE + m + 8] = acc[mi][ni][3];
                    }
                }
            }
            __syncthreads();
            float* ob = out + (size_t)b * CO_ * HW_
                            + (size_t)(half * 128) * HW_ + (size_t)pt * BM;
            #pragma unroll 4
            for (int it = 0; it < 13; it++) {
                int idx = tid + it * NTHR;
                if (idx < 8192) {                    // 128 rows x 64 float2
                    int row = idx >> 6, cp2 = idx & 63;
                    float2 v = *(float2*)&eb[(size_t)row * EPI_STRIDE + cp2 * 2];
                    *(float2*)(ob + (size_t)row * HW_ + cp2 * 2) = v;
                }
            }
            __syncthreads();
        }
    }
}

// ---------------------------------------------------------------------------
extern "C" void kernel_launch(void* const* d_in, const int* in_sizes, int n_in,
                              void* d_out, int out_size)
{
    const float* x   = (const float*)d_in[0];   // [4,256,64,64]
    const float* off = (const float*)d_in[1];   // [4,18,64,64]
    const float* wt  = (const float*)d_in[2];   // [256,256,3,3]
    float* out = (float*)d_out;                 // [4,256,64,64]

    cudaFuncSetAttribute(fused_kernel,
                         cudaFuncAttributeMaxDynamicSharedMemorySize, SM_TOTAL);

    dim3 pgrid(HW_ / 32, CI_ / 32, B_ + 1);     // transpose planes + repack plane
    prep_kernel<<<pgrid, 256>>>(x, wt);

    dim3 grid(HW_ / BM, B_);                    // 32 x 4 = 128 CTAs
    fused_kernel<<<grid, NTHR, SM_TOTAL>>>(off, out);
}

// round 17
// speedup vs baseline: 1.6217x; 1.6217x over previous
#include <cuda_runtime.h>
#include <cuda_fp16.h>
#include <cstdint>
#include <cstddef>

// Problem constants
#define B_    4
#define CI_   256
#define CO_   256
#define H_    64
#define W_    64
#define HW_   4096
#define KK_   9
#define KDIM  2304          // CI_*KK_

// channel-last fp16 input, stored as u32 (half2 pairs): xT[(b*4096+hw)*256 + ci]
__device__ uint32_t g_xT[(size_t)B_ * HW_ * CI_ / 2];   // 8.4 MB
// fp16 repacked weight: w[co][k'] with k' = kk*256 + ci
__device__ __half g_w[(size_t)CO_ * KDIM];              // 1.2 MB

// ---------------------------------------------------------------------------
// Helpers
// ---------------------------------------------------------------------------
__device__ __forceinline__ uint32_t smem_u32(const void* p) {
    uint32_t a;
    asm("{ .reg .u64 t; cvta.to.shared.u64 t, %1; cvt.u32.u64 %0, t; }" : "=r"(a) : "l"(p));
    return a;
}
__device__ __forceinline__ void cp_async16(uint32_t dst, const void* src) {
    asm volatile("cp.async.cg.shared.global [%0], [%1], 16;" :: "r"(dst), "l"(src));
}
#define CP_COMMIT() asm volatile("cp.async.commit_group;" ::: "memory")
#define CP_WAIT1()  asm volatile("cp.async.wait_group 1;" ::: "memory")

__device__ __forceinline__ void ldsm4(uint32_t& r0, uint32_t& r1, uint32_t& r2,
                                      uint32_t& r3, uint32_t addr) {
    asm volatile("ldmatrix.sync.aligned.m8n8.x4.shared.b16 {%0,%1,%2,%3}, [%4];"
                 : "=r"(r0), "=r"(r1), "=r"(r2), "=r"(r3) : "r"(addr));
}
__device__ __forceinline__ void mma16816(float* c, const uint32_t* a, const uint32_t* b) {
    asm volatile(
        "mma.sync.aligned.m16n8k16.row.col.f32.f16.f16.f32 "
        "{%0,%1,%2,%3}, {%4,%5,%6,%7}, {%8,%9}, {%0,%1,%2,%3};"
        : "+f"(c[0]), "+f"(c[1]), "+f"(c[2]), "+f"(c[3])
        : "r"(a[0]), "r"(a[1]), "r"(a[2]), "r"(a[3]), "r"(b[0]), "r"(b[1]));
}
__device__ __forceinline__ void sts128(uint32_t addr, uint32_t v0, uint32_t v1,
                                       uint32_t v2, uint32_t v3) {
    asm volatile("st.shared.v4.b32 [%0], {%1, %2, %3, %4};"
                 :: "r"(addr), "r"(v0), "r"(v1), "r"(v2), "r"(v3) : "memory");
}

// ---------------------------------------------------------------------------
// Kernel 1: merged prep.
//   z < 4 : tiled transpose+convert  x[b][ci][hw] (f32) -> xT[b][hw][ci] (f16)
//   z == 4: grid-stride weight repack g_w[co][kk*256+ci] = (half) W[co][ci][kk]
// ---------------------------------------------------------------------------
__global__ __launch_bounds__(256) void prep_kernel(
    const float* __restrict__ x, const float* __restrict__ w)
{
    int z = blockIdx.z;
    int tid = threadIdx.x;

    if (z < B_) {
        __shared__ float sm[32][33];
        int hw0 = blockIdx.x * 32;
        int ci0 = blockIdx.y * 32;
        int b   = z;
        int tx = tid & 31, ty = tid >> 5;      // (32, 8)

        const float* xb = x + (size_t)b * CI_ * HW_;
        #pragma unroll
        for (int i = 0; i < 4; i++)
            sm[ty + i * 8][tx] = xb[(size_t)(ci0 + ty + i * 8) * HW_ + hw0 + tx];
        __syncthreads();

        uint32_t* xtb = g_xT + (size_t)b * HW_ * CI_ / 2;
        #pragma unroll
        for (int rep = 0; rep < 2; rep++) {
            int t = tid + rep * 256;
            int hwl = t >> 4;                  // 0..31
            int cip = t & 15;                  // ci pair index
            __half2 h2 = __floats2half2_rn(sm[2 * cip][hwl], sm[2 * cip + 1][hwl]);
            xtb[(size_t)(hw0 + hwl) * (CI_ / 2) + ci0 / 2 + cip] = *(uint32_t*)&h2;
        }
    } else {
        int rb = blockIdx.x * gridDim.y + blockIdx.y;     // 0..1023
        for (int ck = rb; ck < CO_ * KK_; ck += 1024) {   // co*9 + kk
            int co = ck / KK_, kk = ck % KK_;
            g_w[(size_t)ck * CI_ + tid] =
                __float2half(w[((size_t)co * CI_ + tid) * KK_ + kk]);
        }
    }
}

// ---------------------------------------------------------------------------
// Kernel 2: fused deformable im2col + HMMA GEMM  (R14 structure)
// CTA: 64 px x 256 co, 256 threads (8 warps, warp tile 64x32), K = 36 x 64.
// 2 CTAs/SM. A gathered in-kernel with QUAD-pixel 128-bit accesses:
// lane = (px-of-quad, 16B ci-octet) -> 4 LDG.128 + HFMA2 + 1 STS.128 per
// group (2 groups/chunk) — half the gather/store instructions of R14.
// B double-buffered via cp.async (B(c+2) after the stage-free barrier,
// wait_group 1). SW128 swizzle on 128B rows: ch ^= (row&7). x2 unrolled
// stages. Coalesced smem epilogue (even stride -> aligned float2).
// ---------------------------------------------------------------------------
#define BM 64
#define BK 64
#define NCH (KDIM / BK)       // 36
#define SM_A0   0             // 2 x 8192  (A: 64 x 64 half)
#define SM_B0   16384         // 2 x 32768 (B: 256 x 64 half)
#define SM_IDX  81920         // int4  [8][8]   (1 KB)
#define SM_WTS  82944         // uint4 [8][8]   (1 KB, half2-broadcast weights)
#define SM_TOTAL 83968
#define EPI_STRIDE 66         // floats per epilogue row (EVEN: 8B-aligned float2)

__global__ __launch_bounds__(256, 2) void fused_kernel(
    const float* __restrict__ offset, float* __restrict__ out)
{
    extern __shared__ char smem[];
    uint32_t sb = smem_u32(smem);
    int tid = threadIdx.x, wid = tid >> 5, l = tid & 31;
    int pt = blockIdx.x;      // pixel tile 0..63
    int b  = blockIdx.y;

    int4*  idx_sm  = (int4*)(smem + SM_IDX)  + wid * 8;
    uint4* wts_sm  = (uint4*)(smem + SM_WTS) + wid * 8;

    const float*  offb = offset + (size_t)b * 18 * HW_;
    const __half* xTb  = (const __half*)g_xT + (size_t)b * HW_ * CI_;

    // bilinear corner offsets/weights for this warp's 8 pixels at tap kk
    auto calc_off = [&](int kk) {
        if (l < 8) {
            int pg = pt * BM + wid * 8 + l;
            int h = pg >> 6, w = pg & 63;
            float offy = offb[(size_t)(2 * kk)     * HW_ + pg];
            float offx = offb[(size_t)(2 * kk + 1) * HW_ + pg];
            int i = kk / 3, j = kk % 3;
            float py = (float)(h + i) + offy;   // padded coords
            float px = (float)(w + j) + offx;
            float y0f = floorf(py), x0f = floorf(px);
            float ly = py - y0f, lx = px - x0f;
            int y0 = (int)y0f - 1, x0 = (int)x0f - 1;   // unpadded
            float wt[4] = { (1.f - ly) * (1.f - lx), (1.f - ly) * lx,
                            ly * (1.f - lx),          ly * lx };
            int fl[4];
            uint32_t wh[4];
            #pragma unroll
            for (int c = 0; c < 4; c++) {
                int yi = y0 + (c >> 1), xi = x0 + (c & 1);
                bool v = (yi >= 0) & (yi < H_) & (xi >= 0) & (xi < W_);
                fl[c] = v ? (yi * W_ + xi) * CI_ : 0;   // half-element offset
                if (!v) wt[c] = 0.f;
                __half2 h2 = __half2half2(__float2half(wt[c]));
                wh[c] = *(uint32_t*)&h2;
            }
            idx_sm[l] = make_int4(fl[0], fl[1], fl[2], fl[3]);
            wts_sm[l] = make_uint4(wh[0], wh[1], wh[2], wh[3]);
        }
        __syncwarp();
    };

    float acc[4][4][4];
    #pragma unroll
    for (int a = 0; a < 4; a++)
        #pragma unroll
        for (int bb = 0; bb < 4; bb++)
            #pragma unroll
            for (int cc = 0; cc < 4; cc++) acc[a][bb][cc] = 0.f;

    // warp tile: 64 px x 32 co;  wn = wid selects co slab
    int wn = wid;
    int laneA_r = l & 15;
    int laneA_c = l >> 4;
    int laneB_r = (l & 7) + ((l >> 4) << 3);
    int laneB_c = (l >> 3) & 1;

    // quad-px gather lane mapping: lane>>3 -> pixel of quad, lane&7 -> ci octet
    int lp = l >> 3;          // 0..3: pixel within group of 4
    int lc = l & 7;           // 16B ci-octet index within 64-ci row

    uint4 cv[4];              // one group in flight: 4 corners x 16B

    auto stage_B = [&](int c, int sn) {
        int k0 = c * BK;
        uint32_t sw = sb + SM_B0 + sn * 32768;
        #pragma unroll
        for (int i = 0; i < 8; i++) {           // 2048 16B chunks / 256 thr
            int id = tid + i * 256;
            int r = id >> 3, ch = id & 7;
            cp_async16(sw + r * 128 + ((ch ^ (r & 7)) << 4),
                       g_w + (size_t)r * KDIM + k0 + ch * 8);
        }
    };
    // gather group h (4 pixels): 4 LDG.128 per lane
    auto gatherG = [&](int c, int h) {
        int cin = (c & 3) * 64;                 // ci block within tap
        const __half* xp = xTb + cin + 8 * lc;  // this lane's ci octet
        int4 f = idx_sm[h * 4 + lp];
        cv[0] = *(const uint4*)(xp + f.x);
        cv[1] = *(const uint4*)(xp + f.y);
        cv[2] = *(const uint4*)(xp + f.z);
        cv[3] = *(const uint4*)(xp + f.w);
    };
    auto convertG = [&](int sn, int h) {
        uint32_t sa = sb + SM_A0 + sn * 8192;
        uint4 w4 = wts_sm[h * 4 + lp];
        __half2 w0 = *(__half2*)&w4.x, w1 = *(__half2*)&w4.y;
        __half2 w2 = *(__half2*)&w4.z, w3 = *(__half2*)&w4.w;
        uint32_t v[4];
        #pragma unroll
        for (int j = 0; j < 4; j++) {
            __half2 r = __hmul2(*((__half2*)&cv[0] + j), w0);
            r = __hfma2(*((__half2*)&cv[1] + j), w1, r);
            r = __hfma2(*((__half2*)&cv[2] + j), w2, r);
            r = __hfma2(*((__half2*)&cv[3] + j), w3, r);
            v[j] = *(uint32_t*)&r;
        }
        int p = wid * 8 + h * 4 + lp;           // A row 0..63
        sts128(sa + p * 128 + ((lc ^ (p & 7)) << 4), v[0], v[1], v[2], v[3]);
    };
    auto mma_steps = [&](int s, int st0) {
        uint32_t sa = sb + SM_A0 + s * 8192;
        uint32_t sw = sb + SM_B0 + s * 32768;
        #pragma unroll
        for (int st = st0; st < st0 + 2; st++) {     // k16 steps
            uint32_t af[4][4];
            #pragma unroll
            for (int mi = 0; mi < 4; mi++) {
                int r = mi * 16 + laneA_r;
                int ch = 2 * st + laneA_c;
                ldsm4(af[mi][0], af[mi][1], af[mi][2], af[mi][3],
                      sa + r * 128 + ((ch ^ (r & 7)) << 4));
            }
            uint32_t bf[4][2];
            #pragma unroll
            for (int nj = 0; nj < 2; nj++) {
                int r = wn * 32 + nj * 16 + laneB_r;
                int ch = 2 * st + laneB_c;
                uint32_t r0, r1, r2, r3;
                ldsm4(r0, r1, r2, r3,
                      sw + r * 128 + ((ch ^ (r & 7)) << 4));
                bf[nj * 2][0] = r0;      bf[nj * 2][1] = r1;
                bf[nj * 2 + 1][0] = r2;  bf[nj * 2 + 1][1] = r3;
            }
            #pragma unroll
            for (int mi = 0; mi < 4; mi++)
                #pragma unroll
                for (int ni = 0; ni < 4; ni++)
                    mma16816(acc[mi][ni], af[mi], bf[ni]);
        }
    };

    // one chunk; s is a literal (x2 unroll) so stage bases const-fold.
    auto chunk_body = [&](int c, int s) {
        int sn = s ^ 1;
        int cn = c + 1;
        bool more = (cn < NCH);
        if (more && ((cn & 3) == 0)) calc_off(cn >> 2);
        if (more) gatherG(cn, 0);
        mma_steps(s, 0);
        if (more) { convertG(sn, 0); gatherG(cn, 1); }
        mma_steps(s, 2);
        if (more) convertG(sn, 1);
        __syncthreads();                 // stage s fully consumed by all warps
        if (c + 2 < NCH) stage_B(c + 2, s);   // a full chunk of slack
        CP_COMMIT();
        CP_WAIT1();                      // B(c+1) resident (all but newest group)
        __syncthreads();                 // visibility of B(c+1) + A(c+1)
    };

    // ---- prologue: chunks 0 and 1 staged ----
    calc_off(0);
    stage_B(0, 0); CP_COMMIT();
    stage_B(1, 1); CP_COMMIT();
    gatherG(0, 0); convertG(0, 0);
    gatherG(0, 1); convertG(0, 1);
    CP_WAIT1();                          // B(0) resident
    __syncthreads();

    // ---- mainloop (unrolled x2: stage index is a literal) ----
    for (int c0 = 0; c0 < NCH; c0 += 2) {
        chunk_body(c0, 0);
        chunk_body(c0 + 1, 1);
    }

    // ---- epilogue: stage acc through smem, then coalesced float2 stores ----
    {
        float* eb = (float*)smem;        // [256][EPI_STRIDE]
        int mrow = l >> 2;
        int ncol = wn * 32 + ((l & 3) << 1);
        #pragma unroll
        for (int mi = 0; mi < 4; mi++) {
            #pragma unroll
            for (int ni = 0; ni < 4; ni++) {
                int m = mrow + mi * 16;
                int n = ncol + ni * 8;
                eb[(size_t)n * EPI_STRIDE + m]           = acc[mi][ni][0];
                eb[(size_t)(n + 1) * EPI_STRIDE + m]     = acc[mi][ni][1];
                eb[(size_t)n * EPI_STRIDE + m + 8]       = acc[mi][ni][2];
                eb[(size_t)(n + 1) * EPI_STRIDE + m + 8] = acc[mi][ni][3];
            }
        }
        __syncthreads();
        float* ob = out + (size_t)b * CO_ * HW_ + (size_t)pt * BM;
        #pragma unroll 4
        for (int k = 0; k < 32; k++) {
            int n = k * 8 + wid;
            float2 v = *(float2*)&eb[(size_t)n * EPI_STRIDE + 2 * l];
            *(float2*)(ob + (size_t)n * HW_ + 2 * l) = v;
        }
    }
}

// ---------------------------------------------------------------------------
extern "C" void kernel_launch(void* const* d_in, const int* in_sizes, int n_in,
                              void* d_out, int out_size)
{
    const float* x   = (const float*)d_in[0];   // [4,256,64,64]
    const float* off = (const float*)d_in[1];   // [4,18,64,64]
    const float* wt  = (const float*)d_in[2];   // [256,256,3,3]
    float* out = (float*)d_out;                 // [4,256,64,64]

    cudaFuncSetAttribute(fused_kernel,
                         cudaFuncAttributeMaxDynamicSharedMemorySize, SM_TOTAL);

    dim3 pgrid(HW_ / 32, CI_ / 32, B_ + 1);     // transpose planes + repack plane
    prep_kernel<<<pgrid, 256>>>(x, wt);

    dim3 grid(HW_ / BM, B_);                    // 64 x 4 = 256 CTAs
    fused_kernel<<<grid, 256, SM_TOTAL>>>(off, out);
}